// round 15
// baseline (speedup 1.0000x reference)
#include <cuda_runtime.h>
#include <cstdint>

#define K_DIM 4096
#define N_DIM 8192
#define INFCAP 100.0f
#define BP_EPS 1e-4f
#define STRIPES 64          // row-stripes for colsum partials
#define CS_BLOCKS 256       // 4 col-blocks x 64 stripes

// ---------------- scratch (no allocation; everything overwritten each call) ----
__device__ float g_part[STRIPES * N_DIM];   // colsum partials (both phases, disjoint lifetimes)
__device__ float g_dope[N_DIM];
__device__ float g_tanh0[N_DIM];            // tanh factor assuming colsum==0 (optimistic)
__device__ float g_prior[N_DIM];            // exact prior (after colsum reduce)
__device__ float g_tanh[N_DIM];             // exact tanh factor
__device__ float g_prod[K_DIM];             // per-row tanh product
__device__ int   g_nzflags[CS_BLOCKS];      // per-block Hxs!=0 flags (unconditional)
__device__ int   g_hxs_nz;                  // reduced flag

__device__ __forceinline__ float tanh_approx(float x) {
    float r;
    asm("tanh.approx.f32 %0, %1;" : "=f"(r) : "f"(x));
    return r;
}

__device__ __forceinline__ float bp_elem(float t, float prod, float s) {
    if (t == 0.f) return 0.f;
    float y = s * __fdividef(prod, t);
    y = fminf(fmaxf(y, -1.f), 1.f);
    float r = __logf(__fdividef(1.f + y, 1.f - y));  // 2*atanh(y)
    return fminf(fmaxf(r, -1.f), 1.f);               // clip absorbs +-inf
}

__device__ __forceinline__ float t_elem(int h, float pr, float hx) {
    return tanh_approx(0.5f * (h ? (pr + BP_EPS - hx) : -hx));
}

// ---------------- K0: dope/phi + optimistic tanh factor (no big deps) ----------------
__global__ __launch_bounds__(256) void k_pre(const float* __restrict__ ps,
                                             const float* __restrict__ Min) {
    int n = blockIdx.x * blockDim.x + threadIdx.x;
    if (n >= N_DIM) return;
    float p0 = ps[2 * n], p1 = ps[2 * n + 1];
    float pn = p1 / (p0 + p1);
    float dope = logf(1.f - pn) - logf(pn);
    float m0 = Min[2 * n], m1 = Min[2 * n + 1];
    float mn = m1 / (m0 + m1);
    float phi = logf(1.f - mn) - logf(mn);
    g_dope[n] = dope;
    float pr0 = fminf(fmaxf(dope + phi, -INFCAP), INFCAP);  // prior if colsum==0
    g_tanh0[n] = tanh_approx(0.5f * (pr0 + BP_EPS));
}

// ---------------- K1: MEGA -- Hxs colsum partials AND optimistic H products ------
// blocks [0,256): colsum role -- block b: cols [ (b&3)*2048, +2048 ) x rows [ (b>>2)*64, +64 )
// blocks [256,2304): product role -- 2 rows per block using g_tanh0
// Both 134 MB streams share one launch => no inter-kernel DRAM drain between them.
__global__ __launch_bounds__(512) void k_mega(const float* __restrict__ Hxs,
                                              const int* __restrict__ H) {
    int tid = threadIdx.x;
    if (blockIdx.x < CS_BLOCKS) {
        const int ROWS = 64;
        int bx = blockIdx.x & 3, by = blockIdx.x >> 2;
        int cbase = bx * 2048 + tid * 4;
        int r0 = by * ROWS;
        const float4* p = (const float4*)(Hxs + (size_t)r0 * N_DIM + cbase);
        float4 a = make_float4(0.f, 0.f, 0.f, 0.f);
        bool nz = false;
#pragma unroll 8
        for (int r = 0; r < ROWS; r++) {
            float4 v = p[(size_t)r * (N_DIM / 4)];
            a.x += v.x; a.y += v.y; a.z += v.z; a.w += v.w;
            nz = nz || (v.x != 0.f) || (v.y != 0.f) || (v.z != 0.f) || (v.w != 0.f);
        }
        *(float4*)&g_part[(size_t)by * N_DIM + cbase] = a;
        bool bnz = __syncthreads_or(nz);
        if (tid == 0) g_nzflags[blockIdx.x] = bnz ? 1 : 0;   // unconditional write
    } else {
        __shared__ float warp_prod[2][16];
        int k0 = (blockIdx.x - CS_BLOCKS) * 2;
        const int4* h4a = (const int4*)(H + (size_t)k0 * N_DIM);
        const int4* h4b = (const int4*)(H + (size_t)(k0 + 1) * N_DIM);
        const float4* th4 = (const float4*)g_tanh0;
        float pa = 1.f, pb = 1.f;
#pragma unroll
        for (int i = 0; i < 4; i++) {
            int idx = tid + i * 512;
            int4 ha = h4a[idx];
            int4 hb = h4b[idx];
            float4 t = th4[idx];
            pa *= (ha.x ? t.x : 1.f) * (ha.y ? t.y : 1.f)
                * (ha.z ? t.z : 1.f) * (ha.w ? t.w : 1.f);
            pb *= (hb.x ? t.x : 1.f) * (hb.y ? t.y : 1.f)
                * (hb.z ? t.z : 1.f) * (hb.w ? t.w : 1.f);
        }
#pragma unroll
        for (int off = 16; off; off >>= 1) {
            pa *= __shfl_xor_sync(0xffffffffu, pa, off);
            pb *= __shfl_xor_sync(0xffffffffu, pb, off);
        }
        if ((tid & 31) == 0) {
            warp_prod[0][tid >> 5] = pa;
            warp_prod[1][tid >> 5] = pb;
        }
        __syncthreads();
        if (tid < 32) {
            int which = tid >> 4;
            float q = warp_prod[which][tid & 15];
#pragma unroll
            for (int off = 8; off; off >>= 1) q *= __shfl_xor_sync(0xffffffffu, q, off, 16);
            if ((tid & 15) == 0) g_prod[k0 + which] = q;
        }
    }
}

// ---------------- K2: reduce partials -> exact prior/tanh; reduce nz flag ----------
__global__ __launch_bounds__(256) void k_prior(const float* __restrict__ ps,
                                               const float* __restrict__ Min) {
    int n = blockIdx.x * blockDim.x + threadIdx.x;
    if (n < N_DIM) {
        float cs = 0.f;
#pragma unroll 8
        for (int j = 0; j < STRIPES; j++) cs += g_part[(size_t)j * N_DIM + n];
        float p0 = ps[2 * n], p1 = ps[2 * n + 1];
        float pn = p1 / (p0 + p1);
        float dope = logf(1.f - pn) - logf(pn);
        float m0 = Min[2 * n], m1 = Min[2 * n + 1];
        float mn = m1 / (m0 + m1);
        float phi = logf(1.f - mn) - logf(mn);
        float pr = fminf(fmaxf(dope + phi + cs, -INFCAP), INFCAP);
        g_prior[n] = pr;
        g_tanh[n] = tanh_approx(0.5f * (pr + BP_EPS));  // == g_tanh0 when cs==0
    }
    if (blockIdx.x == 0) {
        bool any = __syncthreads_or(g_nzflags[threadIdx.x] != 0);
        if (threadIdx.x == 0) g_hxs_nz = any ? 1 : 0;
    }
}

// ---------------- K3: output writer ----------------
// Fast path (Hxs==0): optimistic g_prod is EXACT. prod==0 -> pure zero-write;
// prod!=0 -> o = h ? bp_elem(g_tanh[n], prod, s) : 0 (t for h=0 is tanh(-0)=0).
// Slow path (general): full exact fused recompute; overwrites g_prod for colsum2.
__global__ __launch_bounds__(512) void k_write(const float* __restrict__ Hxs,
                                               const int* __restrict__ H,
                                               const int* __restrict__ x,
                                               float* __restrict__ out_Hxs) {
    __shared__ float warp_prod[16];
    int k = blockIdx.x;
    int tid = threadIdx.x;
    float4* o4 = (float4*)(out_Hxs + (size_t)k * N_DIM);

    if (g_hxs_nz == 0) {
        float prod = g_prod[k];
        if (prod == 0.f) {
            float4 z = make_float4(0.f, 0.f, 0.f, 0.f);
#pragma unroll
            for (int i = 0; i < 4; i++) o4[tid + i * 512] = z;
        } else {
            const int4*   h4  = (const int4*)(H + (size_t)k * N_DIM);
            const float4* th4 = (const float4*)g_tanh;
            float s = (float)(1 - 2 * x[k]);
#pragma unroll
            for (int i = 0; i < 4; i++) {
                int idx = tid + i * 512;
                int4   h = h4[idx];
                float4 t = th4[idx];
                float4 o;
                o.x = h.x ? bp_elem(t.x, prod, s) : 0.f;
                o.y = h.y ? bp_elem(t.y, prod, s) : 0.f;
                o.z = h.z ? bp_elem(t.z, prod, s) : 0.f;
                o.w = h.w ? bp_elem(t.w, prod, s) : 0.f;
                o4[idx] = o;
            }
        }
    } else {
        // ---- exact fused path for general inputs ----
        const float4* hx4 = (const float4*)(Hxs + (size_t)k * N_DIM);
        const int4*   h4  = (const int4*)(H + (size_t)k * N_DIM);
        const float4* pr4 = (const float4*)g_prior;
        float s = (float)(1 - 2 * x[k]);
        float p = 1.f;
        float4 tt[4];
#pragma unroll
        for (int i = 0; i < 4; i++) {
            int idx = tid + i * 512;
            float4 hx = hx4[idx];
            int4   h  = h4[idx];
            float4 pr = pr4[idx];
            float4 t;
            t.x = t_elem(h.x, pr.x, hx.x);
            t.y = t_elem(h.y, pr.y, hx.y);
            t.z = t_elem(h.z, pr.z, hx.z);
            t.w = t_elem(h.w, pr.w, hx.w);
            tt[i] = t;
            p *= ((t.x == 0.f) ? 1.f : t.x) * ((t.y == 0.f) ? 1.f : t.y)
               * ((t.z == 0.f) ? 1.f : t.z) * ((t.w == 0.f) ? 1.f : t.w);
        }
#pragma unroll
        for (int off = 16; off; off >>= 1) p *= __shfl_xor_sync(0xffffffffu, p, off);
        if ((tid & 31) == 0) warp_prod[tid >> 5] = p;
        __syncthreads();
        if (tid < 16) {
            float q = warp_prod[tid];
#pragma unroll
            for (int off = 8; off; off >>= 1) q *= __shfl_xor_sync(0x0000ffffu, q, off);
            if (tid == 0) { warp_prod[0] = q; g_prod[k] = q; }  // exact prod for colsum2
        }
        __syncthreads();
        float prod = warp_prod[0];
#pragma unroll
        for (int i = 0; i < 4; i++) {
            int idx = tid + i * 512;
            float4 t = tt[i];
            float4 o;
            o.x = bp_elem(t.x, prod, s);
            o.y = bp_elem(t.y, prod, s);
            o.z = bp_elem(t.z, prod, s);
            o.w = bp_elem(t.w, prod, s);
            o4[idx] = o;
        }
    }
}

// ---------------- K4: column partial sums of Hxs_new, skipping zero rows ----------
__global__ __launch_bounds__(256) void k_colsum2(const float* __restrict__ M) {
    const int ROWS = 64;
    int tid = threadIdx.x;
    int cbase = blockIdx.x * 1024 + tid * 4;
    int r0 = blockIdx.y * ROWS;
    const float4* p = (const float4*)(M + (size_t)r0 * N_DIM + cbase);
    float4 a = make_float4(0.f, 0.f, 0.f, 0.f);
    for (int r = 0; r < ROWS; r++) {
        if (g_prod[r0 + r] != 0.f) {      // zero-product rows are exactly 0: skip
            float4 v = p[(size_t)r * (N_DIM / 4)];
            a.x += v.x; a.y += v.y; a.z += v.z; a.w += v.w;
        }
    }
    *(float4*)&g_part[(size_t)blockIdx.y * N_DIM + cbase] = a;
}

// ---------------- K5: reduce partials -> output beliefs ----------------
__global__ __launch_bounds__(256) void k_out(float* __restrict__ out_M) {
    int n = blockIdx.x * blockDim.x + threadIdx.x;
    if (n >= N_DIM) return;
    float cs2 = 0.f;
#pragma unroll 8
    for (int j = 0; j < STRIPES; j++) cs2 += g_part[(size_t)j * N_DIM + n];
    float z = (1.f - tanhf((cs2 + g_dope[n]) * 0.5f)) * 0.5f;
    out_M[2 * n + 0] = 1.f - z;
    out_M[2 * n + 1] = z;
}

extern "C" void kernel_launch(void* const* d_in, const int* in_sizes, int n_in,
                              void* d_out, int out_size) {
    const float* ps  = (const float*)d_in[0];
    const float* Min = (const float*)d_in[1];
    const float* Hxs = (const float*)d_in[2];
    const int*   x   = (const int*)d_in[3];
    const int*   H   = (const int*)d_in[4];

    float* out     = (float*)d_out;
    float* out_M   = out;                 // M_out [N,2] first
    float* out_Hxs = out + 2 * N_DIM;     // Hxs_new [K,N] second

    k_pre    <<<N_DIM / 256, 256>>>(ps, Min);
    k_mega   <<<CS_BLOCKS + K_DIM / 2, 512>>>(Hxs, H);
    k_prior  <<<N_DIM / 256, 256>>>(ps, Min);
    k_write  <<<K_DIM, 512>>>(Hxs, H, x, out_Hxs);
    k_colsum2<<<dim3(N_DIM / 1024, STRIPES), 256>>>(out_Hxs);
    k_out    <<<N_DIM / 256, 256>>>(out_M);
}

// round 16
// speedup vs baseline: 1.0678x; 1.0678x over previous
#include <cuda_runtime.h>
#include <cstdint>

#define K_DIM 4096
#define N_DIM 8192
#define INFCAP 100.0f
#define BP_EPS 1e-4f
#define STRIPES 64          // row-stripes for colsum partials
#define CS_BLOCKS 256       // 4 col-blocks x 64 stripes
#define PROD_BLOCKS (K_DIM / 4)

// ---------------- scratch (no allocation; everything overwritten each call) ----
__device__ float g_part[STRIPES * N_DIM];   // colsum partials (2 MB, L2-resident)
__device__ float g_dope[N_DIM];
__device__ float g_dopephi[N_DIM];          // dope+phi (unclipped)
__device__ float g_tanh0[N_DIM];            // tanh factor assuming colsum==0 (optimistic)
__device__ float g_prior[N_DIM];            // exact prior (after colsum reduce)
__device__ float g_tanh[N_DIM];             // exact tanh factor
__device__ float g_prod[K_DIM];             // per-row tanh product
__device__ float g_colsum2[N_DIM];          // colsum of Hxs_new (zeroed by k_pre)
__device__ int   g_nzflags[CS_BLOCKS];      // per-block Hxs!=0 flags (unconditional)
__device__ int   g_hxs_nz;                  // reduced flag

__device__ __forceinline__ float tanh_approx(float x) {
    float r;
    asm("tanh.approx.f32 %0, %1;" : "=f"(r) : "f"(x));
    return r;
}

__device__ __forceinline__ float bp_elem(float t, float prod, float s) {
    if (t == 0.f) return 0.f;
    float y = s * __fdividef(prod, t);
    y = fminf(fmaxf(y, -1.f), 1.f);
    float r = __logf(__fdividef(1.f + y, 1.f - y));  // 2*atanh(y)
    return fminf(fmaxf(r, -1.f), 1.f);               // clip absorbs +-inf
}

__device__ __forceinline__ float t_elem(int h, float pr, float hx) {
    return tanh_approx(0.5f * (h ? (pr + BP_EPS - hx) : -hx));
}

// ---------------- K0: dope/phi + optimistic tanh factor + zero colsum2 ------------
__global__ __launch_bounds__(256) void k_pre(const float* __restrict__ ps,
                                             const float* __restrict__ Min) {
    int n = blockIdx.x * blockDim.x + threadIdx.x;
    if (n >= N_DIM) return;
    float p0 = ps[2 * n], p1 = ps[2 * n + 1];
    float pn = p1 / (p0 + p1);
    float dope = logf(1.f - pn) - logf(pn);
    float m0 = Min[2 * n], m1 = Min[2 * n + 1];
    float mn = m1 / (m0 + m1);
    float phi = logf(1.f - mn) - logf(mn);
    g_dope[n] = dope;
    float dp = dope + phi;
    g_dopephi[n] = dp;
    float pr0 = fminf(fmaxf(dp, -INFCAP), INFCAP);  // prior if colsum==0
    g_tanh0[n] = tanh_approx(0.5f * (pr0 + BP_EPS));
    g_colsum2[n] = 0.f;                             // accumulated by k_write
}

// ---------------- K1: MEGA -- Hxs colsum partials AND optimistic H products ------
// blocks [0,256): colsum role; blocks [256,1280): product role, 4 rows each
// (two 2-row passes; second pass hits g_tanh0 L1-warm).
__global__ __launch_bounds__(512) void k_mega(const float* __restrict__ Hxs,
                                              const int* __restrict__ H) {
    int tid = threadIdx.x;
    if (blockIdx.x < CS_BLOCKS) {
        const int ROWS = 64;
        int bx = blockIdx.x & 3, by = blockIdx.x >> 2;
        int cbase = bx * 2048 + tid * 4;
        int r0 = by * ROWS;
        const float4* p = (const float4*)(Hxs + (size_t)r0 * N_DIM + cbase);
        float4 a = make_float4(0.f, 0.f, 0.f, 0.f);
        bool nz = false;
#pragma unroll 8
        for (int r = 0; r < ROWS; r++) {
            float4 v = p[(size_t)r * (N_DIM / 4)];
            a.x += v.x; a.y += v.y; a.z += v.z; a.w += v.w;
            nz = nz || (v.x != 0.f) || (v.y != 0.f) || (v.z != 0.f) || (v.w != 0.f);
        }
        *(float4*)&g_part[(size_t)by * N_DIM + cbase] = a;
        bool bnz = __syncthreads_or(nz);
        if (tid == 0) g_nzflags[blockIdx.x] = bnz ? 1 : 0;   // unconditional write
    } else {
        __shared__ float warp_prod[4][16];
        int k0 = (blockIdx.x - CS_BLOCKS) * 4;
        const float4* th4 = (const float4*)g_tanh0;
        float pr_[4] = {1.f, 1.f, 1.f, 1.f};
#pragma unroll
        for (int j = 0; j < 2; j++) {
            const int4* h4a = (const int4*)(H + (size_t)(k0 + 2 * j) * N_DIM);
            const int4* h4b = (const int4*)(H + (size_t)(k0 + 2 * j + 1) * N_DIM);
            float pa = 1.f, pb = 1.f;
#pragma unroll
            for (int i = 0; i < 4; i++) {
                int idx = tid + i * 512;
                int4 ha = h4a[idx];
                int4 hb = h4b[idx];
                float4 t = th4[idx];
                pa *= (ha.x ? t.x : 1.f) * (ha.y ? t.y : 1.f)
                    * (ha.z ? t.z : 1.f) * (ha.w ? t.w : 1.f);
                pb *= (hb.x ? t.x : 1.f) * (hb.y ? t.y : 1.f)
                    * (hb.z ? t.z : 1.f) * (hb.w ? t.w : 1.f);
            }
            pr_[2 * j] = pa; pr_[2 * j + 1] = pb;
        }
#pragma unroll
        for (int r = 0; r < 4; r++) {
#pragma unroll
            for (int off = 16; off; off >>= 1) pr_[r] *= __shfl_xor_sync(0xffffffffu, pr_[r], off);
        }
        if ((tid & 31) == 0) {
#pragma unroll
            for (int r = 0; r < 4; r++) warp_prod[r][tid >> 5] = pr_[r];
        }
        __syncthreads();
        if (tid < 64) {
            int grp = tid >> 4;
            float q = warp_prod[grp][tid & 15];
#pragma unroll
            for (int off = 8; off; off >>= 1) q *= __shfl_xor_sync(0xffffffffu, q, off, 16);
            if ((tid & 15) == 0) g_prod[k0 + grp] = q;
        }
    }
}

// ---------------- K2: reduce partials -> exact prior/tanh; reduce nz flag ----------
__global__ __launch_bounds__(256) void k_prior() {
    int n = blockIdx.x * blockDim.x + threadIdx.x;
    if (n < N_DIM) {
        float cs = 0.f;
#pragma unroll 8
        for (int j = 0; j < STRIPES; j++) cs += g_part[(size_t)j * N_DIM + n];
        float pr = fminf(fmaxf(g_dopephi[n] + cs, -INFCAP), INFCAP);
        g_prior[n] = pr;
        g_tanh[n] = tanh_approx(0.5f * (pr + BP_EPS));  // == g_tanh0 when cs==0
    }
    if (blockIdx.x == 0) {
        bool any = __syncthreads_or(g_nzflags[threadIdx.x] != 0);
        if (threadIdx.x == 0) g_hxs_nz = any ? 1 : 0;
    }
}

// ---------------- K3: output writer + fused colsum2 ----------------
// Fast path (Hxs==0): optimistic g_prod is EXACT. prod==0 -> pure zero-write,
// zero atomics. prod!=0 -> exact H-masked outputs + atomic colsum2.
// Slow path (general): exact fused recompute + atomic colsum2.
__global__ __launch_bounds__(512) void k_write(const float* __restrict__ Hxs,
                                               const int* __restrict__ H,
                                               const int* __restrict__ x,
                                               float* __restrict__ out_Hxs) {
    __shared__ float warp_prod[16];
    int k = blockIdx.x;
    int tid = threadIdx.x;
    float4* o4 = (float4*)(out_Hxs + (size_t)k * N_DIM);

    if (g_hxs_nz == 0) {
        float prod = g_prod[k];
        if (prod == 0.f) {
            float4 z = make_float4(0.f, 0.f, 0.f, 0.f);
#pragma unroll
            for (int i = 0; i < 4; i++) o4[tid + i * 512] = z;
        } else {
            const int4*   h4  = (const int4*)(H + (size_t)k * N_DIM);
            const float4* th4 = (const float4*)g_tanh;
            float s = (float)(1 - 2 * x[k]);
#pragma unroll
            for (int i = 0; i < 4; i++) {
                int idx = tid + i * 512;
                int4   h = h4[idx];
                float4 t = th4[idx];
                float4 o;
                o.x = h.x ? bp_elem(t.x, prod, s) : 0.f;
                o.y = h.y ? bp_elem(t.y, prod, s) : 0.f;
                o.z = h.z ? bp_elem(t.z, prod, s) : 0.f;
                o.w = h.w ? bp_elem(t.w, prod, s) : 0.f;
                o4[idx] = o;
                int c = idx * 4;
                atomicAdd(&g_colsum2[c + 0], o.x);
                atomicAdd(&g_colsum2[c + 1], o.y);
                atomicAdd(&g_colsum2[c + 2], o.z);
                atomicAdd(&g_colsum2[c + 3], o.w);
            }
        }
    } else {
        // ---- exact fused path for general inputs ----
        const float4* hx4 = (const float4*)(Hxs + (size_t)k * N_DIM);
        const int4*   h4  = (const int4*)(H + (size_t)k * N_DIM);
        const float4* pr4 = (const float4*)g_prior;
        float s = (float)(1 - 2 * x[k]);
        float p = 1.f;
        float4 tt[4];
#pragma unroll
        for (int i = 0; i < 4; i++) {
            int idx = tid + i * 512;
            float4 hx = hx4[idx];
            int4   h  = h4[idx];
            float4 pr = pr4[idx];
            float4 t;
            t.x = t_elem(h.x, pr.x, hx.x);
            t.y = t_elem(h.y, pr.y, hx.y);
            t.z = t_elem(h.z, pr.z, hx.z);
            t.w = t_elem(h.w, pr.w, hx.w);
            tt[i] = t;
            p *= ((t.x == 0.f) ? 1.f : t.x) * ((t.y == 0.f) ? 1.f : t.y)
               * ((t.z == 0.f) ? 1.f : t.z) * ((t.w == 0.f) ? 1.f : t.w);
        }
#pragma unroll
        for (int off = 16; off; off >>= 1) p *= __shfl_xor_sync(0xffffffffu, p, off);
        if ((tid & 31) == 0) warp_prod[tid >> 5] = p;
        __syncthreads();
        if (tid < 16) {
            float q = warp_prod[tid];
#pragma unroll
            for (int off = 8; off; off >>= 1) q *= __shfl_xor_sync(0x0000ffffu, q, off);
            if (tid == 0) warp_prod[0] = q;
        }
        __syncthreads();
        float prod = warp_prod[0];
        bool nzrow = (prod != 0.f);
#pragma unroll
        for (int i = 0; i < 4; i++) {
            int idx = tid + i * 512;
            float4 t = tt[i];
            float4 o;
            o.x = bp_elem(t.x, prod, s);
            o.y = bp_elem(t.y, prod, s);
            o.z = bp_elem(t.z, prod, s);
            o.w = bp_elem(t.w, prod, s);
            o4[idx] = o;
            if (nzrow) {
                int c = idx * 4;
                atomicAdd(&g_colsum2[c + 0], o.x);
                atomicAdd(&g_colsum2[c + 1], o.y);
                atomicAdd(&g_colsum2[c + 2], o.z);
                atomicAdd(&g_colsum2[c + 3], o.w);
            }
        }
    }
}

// ---------------- K4: output beliefs ----------------
__global__ __launch_bounds__(256) void k_out(float* __restrict__ out_M) {
    int n = blockIdx.x * blockDim.x + threadIdx.x;
    if (n >= N_DIM) return;
    float z = (1.f - tanhf((g_colsum2[n] + g_dope[n]) * 0.5f)) * 0.5f;
    out_M[2 * n + 0] = 1.f - z;
    out_M[2 * n + 1] = z;
}

extern "C" void kernel_launch(void* const* d_in, const int* in_sizes, int n_in,
                              void* d_out, int out_size) {
    const float* ps  = (const float*)d_in[0];
    const float* Min = (const float*)d_in[1];
    const float* Hxs = (const float*)d_in[2];
    const int*   x   = (const int*)d_in[3];
    const int*   H   = (const int*)d_in[4];

    float* out     = (float*)d_out;
    float* out_M   = out;                 // M_out [N,2] first
    float* out_Hxs = out + 2 * N_DIM;     // Hxs_new [K,N] second

    k_pre  <<<N_DIM / 256, 256>>>(ps, Min);
    k_mega <<<CS_BLOCKS + PROD_BLOCKS, 512>>>(Hxs, H);
    k_prior<<<N_DIM / 256, 256>>>();
    k_write<<<K_DIM, 512>>>(Hxs, H, x, out_Hxs);
    k_out  <<<N_DIM / 256, 256>>>(out_M);
}